// round 11
// baseline (speedup 1.0000x reference)
#include <cuda_runtime.h>
#include <cstdint>

#define T_STEPS 512
#define BATCH   512
#define INDIM   4
#define AUXDIM  28
#define OUTDIM  32
#define GDIM    64
#define NCTA    64
#define BC      8          // batch rows per CTA
#define NTHREADS 640
#define JCOLS   1184       // 1024 (W_r) | 128 (W_i) | 32 (W_o)
#define JPAIRS  592
#define CACHED_JP 288      // jp < 288 -> caching loads (576 cols = 147KB, L1-resident)

typedef unsigned long long ull;

// ---------------- device globals (scratch; no allocation allowed) -------------
__device__ __align__(16) float g_W[64 * JCOLS];  // [k][j] transposed packed weights
__device__ float g_bias[JCOLS];
__device__ float g_expWs[32 * 64];         // exp(W_s)[o][g]
__device__ float g_ov0base[64];            // sum_o b0[o]*exp(W_s)[o][g]
__device__ float g_sigWrT[64 * 32];        // sigmoid(W_rm^T)[k][j]
__device__ __align__(16) ull g_slot[(T_STEPS + 1) * NCTA];  // (tag<<32)|float-bits

__device__ __forceinline__ void ffma2(ull &d, ull a, ull b) {
    asm volatile("fma.rn.f32x2 %0, %1, %2, %0;" : "+l"(d) : "l"(a), "l"(b));
}
__device__ __forceinline__ float wsum32(float v) {
#pragma unroll
    for (int s = 16; s; s >>= 1) v += __shfl_xor_sync(0xffffffffu, v, s);
    return v;
}
__device__ __forceinline__ float sigmoidf_(float x) { return 1.f / (1.f + expf(-x)); }

// Morally-strong relaxed gpu-scope handshake (single 8B word carries tag+value:
// strong ops are single-copy atomic + coherently visible; no fence, no L1 flush).
__device__ __forceinline__ float wait_slot(const ull* p, unsigned tag) {
    ull v;
    do {
        asm volatile("ld.relaxed.gpu.global.u64 %0, [%1];"
                     : "=l"(v) : "l"(p) : "memory");
    } while ((unsigned)(v >> 32) != tag);
    return __uint_as_float((unsigned)v);
}
__device__ __forceinline__ void post_slot(ull* p, ull pk) {
    asm volatile("st.relaxed.gpu.global.u64 [%0], %1;"
                 :: "l"(p), "l"(pk) : "memory");
}

// ---------------- prep kernel: transpose/pack weights, reset sync state -------
__global__ void prep_kernel(const float* __restrict__ Wi, const float* __restrict__ bi,
                            const float* __restrict__ Wr, const float* __restrict__ br,
                            const float* __restrict__ Wo, const float* __restrict__ bo,
                            const float* __restrict__ Ws, const float* __restrict__ Wrm,
                            const float* __restrict__ b0) {
    int idx = blockIdx.x * blockDim.x + threadIdx.x;
    int stride = gridDim.x * blockDim.x;
    for (int i = idx; i < 64 * JCOLS; i += stride) {
        int k = i / JCOLS, j = i % JCOLS;
        float v;
        if (j < 1024)       v = Wr[j * 64 + k];
        else if (j < 1152)  v = Wi[(j - 1024) * 64 + k];
        else                v = Wo[(j - 1152) * 64 + k];
        g_W[k * JCOLS + j] = v;
    }
    for (int j = idx; j < JCOLS; j += stride)
        g_bias[j] = (j < 1024) ? br[j] : ((j < 1152) ? bi[j - 1024] : bo[j - 1152]);
    for (int i = idx; i < 32 * 64; i += stride) g_expWs[i] = expf(Ws[i]);
    for (int i = idx; i < 64 * 32; i += stride) {
        int k = i / 32, j = i % 32;
        g_sigWrT[i] = 1.f / (1.f + expf(-Wrm[j * 64 + k]));
    }
    for (int g = idx; g < 64; g += stride) {
        float s = 0.f;
        for (int o = 0; o < 32; o++) s += b0[o] * expf(Ws[o * 64 + g]);
        g_ov0base[g] = s;
    }
    // reset ALL slots (stale tags from a previous graph replay would alias),
    // then arm step 0 with partial |c| = 0, tag = 1.
    for (int i = idx; i < (T_STEPS + 1) * NCTA; i += stride) g_slot[i] = 0ull;
    for (int i = idx; i < NCTA; i += stride) g_slot[i] = (1ull << 32);
}

// ---------------- GEMM inner loop (col-pair f32x2, dup'd feat) ----------------
template<bool CG>
__device__ __forceinline__ void run_gemm(const float* __restrict__ wcol,
                                         const float2* __restrict__ sfX,
                                         const float2* __restrict__ sfC,
                                         ull accA[8], ull accB[8]) {
#pragma unroll 8
    for (int k = 0; k < 32; k++) {
        const float* p = wcol + k * JCOLS;
        ull w = CG ? __ldcg((const ull*)p) : *(const ull*)p;
        const longlong2* f = (const longlong2*)(sfX + k * 8);
        longlong2 f01 = f[0], f23 = f[1], f45 = f[2], f67 = f[3];
        ffma2(accA[0], w, (ull)f01.x); ffma2(accA[1], w, (ull)f01.y);
        ffma2(accA[2], w, (ull)f23.x); ffma2(accA[3], w, (ull)f23.y);
        ffma2(accA[4], w, (ull)f45.x); ffma2(accA[5], w, (ull)f45.y);
        ffma2(accA[6], w, (ull)f67.x); ffma2(accA[7], w, (ull)f67.y);
    }
#pragma unroll 8
    for (int k = 0; k < 32; k++) {
        const float* p = wcol + (k + 32) * JCOLS;
        ull w = CG ? __ldcg((const ull*)p) : *(const ull*)p;
        const longlong2* f = (const longlong2*)(sfC + k * 8);
        longlong2 f01 = f[0], f23 = f[1], f45 = f[2], f67 = f[3];
        ffma2(accB[0], w, (ull)f01.x); ffma2(accB[1], w, (ull)f01.y);
        ffma2(accB[2], w, (ull)f23.x); ffma2(accB[3], w, (ull)f23.y);
        ffma2(accB[4], w, (ull)f45.x); ffma2(accB[5], w, (ull)f45.y);
        ffma2(accB[6], w, (ull)f67.x); ffma2(accB[7], w, (ull)f67.y);
    }
}

// ---------------- persistent recurrent kernel --------------------------------
__global__ void __launch_bounds__(NTHREADS, 1) lstm_kernel(
    const float* __restrict__ xm, const float* __restrict__ xa,
    const float* __restrict__ lng, const float* __restrict__ lnb,
    float* __restrict__ out) {
    __shared__ __align__(16) float2 s_featX[2][32][8];  // x-part, double-buffered
    __shared__ __align__(16) float2 s_featC[32][8];     // c-part (raw carry, dup)
    __shared__ float s_c[8][32];
    __shared__ float s_P[8][1024];
    __shared__ float s_I[8][128];
    __shared__ float s_go[8][32];
    __shared__ float s_tov0[8][64];
    __shared__ float s_ov1[8][32];
    __shared__ float s_m1[8][32];
    __shared__ float s_m2[8][32];
    __shared__ float s_rsR[8][32];
    __shared__ float s_rsI[8][4];
    __shared__ float s_abs[8];
    __shared__ float s_invS;

    const int tid  = threadIdx.x;
    const int cta  = blockIdx.x;
    const int lane = tid & 31;
    const int warp = tid >> 5;

    const int  jp = tid;
    const bool gemm_active = (jp < JPAIRS);
    const float* wcol = g_W + 2 * jp;
    float bias0 = 0.f, bias1 = 0.f;
    if (gemm_active) { bias0 = g_bias[2 * jp]; bias1 = g_bias[2 * jp + 1]; }

    const int fb_k = tid >> 3, fb_b = tid & 7;   // feat build (tid<512)
    const int ov_b = tid >> 6, ov_g = tid & 63;  // ov0 raw    (tid<512)

    float r_lng = 0.f, r_lnb = 0.f;
    if (warp < 8) { r_lng = lng[lane]; r_lnb = lnb[lane]; }

    // init: zero carry state, preload x for t=0, build initial feat buffers
    for (int i = tid; i < 8 * 32; i += NTHREADS) ((float*)s_c)[i] = 0.f;
    for (int i = tid; i < 32 * 8; i += NTHREADS)
        ((float2*)s_featC)[i] = make_float2(0.f, 0.f);
    float rx = 0.f;
    const int gb = cta * BC + fb_b;
    if (tid < 512 && fb_k < 32) {
        rx = (fb_k < INDIM) ? xm[(size_t)gb * INDIM + fb_k]
                            : xa[(size_t)gb * AUXDIM + (fb_k - INDIM)];
        s_featX[0][fb_k][fb_b] = make_float2(rx, rx);
    }

    const size_t OSZ = (size_t)T_STEPS * BATCH * OUTDIM;
    float* out_h  = out;
    float* out_c  = out + OSZ;
    float* out_o  = out + 2 * OSZ;
    float* out_mr = out + 3 * OSZ;
    float* out_op = out + 4 * OSZ;
    float* out_mf = out + 5 * OSZ;
    float* out_of = out + 6 * OSZ;

    __syncthreads();

    for (int t = 0; t < T_STEPS; t++) {
        const float2* sfX = &s_featX[t & 1][0][0];

        // ---- GEMM phase (no P0: feat was staged by prior epilogue/P4) -----
        ull accA[8], accB[8];
        if (gemm_active) {
#pragma unroll
            for (int b = 0; b < 8; b++) { accA[b] = 0ull; accB[b] = 0ull; }
            if (jp < CACHED_JP) run_gemm<false>(wcol, sfX, &s_featC[0][0], accA, accB);
            else                run_gemm<true >(wcol, sfX, &s_featC[0][0], accA, accB);
        }
        // ov0 raw: c @ exp(W_s)  (one output per thread, tid<512)
        float accC = 0.f;
        if (tid < 512) {
#pragma unroll 8
            for (int o = 0; o < 32; o++) accC += s_c[ov_b][o] * g_expWs[o * 64 + ov_g];
        }
        // prefetch next step's x into rx (consumed by this step's epilogue)
        if (tid < 512 && fb_k < 32 && t + 1 < T_STEPS) {
            rx = (fb_k < INDIM)
                     ? xm[(size_t)(t + 1) * BATCH * INDIM + (size_t)gb * INDIM + fb_k]
                     : xa[(size_t)(t + 1) * BATCH * AUXDIM + (size_t)gb * AUXDIM + (fb_k - INDIM)];
        }
        // warp 19 (idle in GEMM): handshake spin fully overlaps the GEMM
        if (warp == 19) {
            const unsigned tag = (unsigned)(t + 1);
            const ull* base = g_slot + (size_t)t * NCTA;
            float p0 = wait_slot(base + lane, tag);
            float p1 = wait_slot(base + lane + 32, tag);
            float v = wsum32(p0 + p1);
            if (lane == 0) s_invS = 1.f / (v + 1e-5f);
        }
        __syncthreads();                         // B1: invS visible; GEMM reads done
        const float invS = s_invS;

        // ---- Epilogue: logits, activations, fused row-sums; stage next x ---
        if (gemm_active) {
            const int j0 = 2 * jp;
            float hs[8];
#pragma unroll
            for (int b = 0; b < 8; b++) {
                float2 a  = *(float2*)&accA[b];
                float2 bb = *(float2*)&accB[b];
                float v0 = fmaf(invS, bb.x, a.x) + bias0;
                float v1 = fmaf(invS, bb.y, a.y) + bias1;
                if (jp < 512) {                       // W_r: relu
                    v0 = fmaxf(v0, 0.f); v1 = fmaxf(v1, 0.f);
                    *(float2*)&s_P[b][j0] = make_float2(v0, v1);
                    hs[b] = v0 + v1;
                } else if (jp < 576) {                // W_i: sigmoid
                    v0 = sigmoidf_(v0); v1 = sigmoidf_(v1);
                    *(float2*)&s_I[b][j0 - 1024] = make_float2(v0, v1);
                    hs[b] = v0 + v1;
                } else {                              // W_o: sigmoid
                    *(float2*)&s_go[b][j0 - 1152] =
                        make_float2(sigmoidf_(v0), sigmoidf_(v1));
                }
            }
            if (jp < 576) {   // 16-lane row-sum: 16 consecutive threads = one row
#pragma unroll
                for (int b = 0; b < 8; b++) {
#pragma unroll
                    for (int s = 1; s < 16; s <<= 1)
                        hs[b] += __shfl_xor_sync(0xffffffffu, hs[b], s);
                }
                if ((jp & 15) == 0) {
                    if (jp < 512) {
                        const int o = jp >> 4;
#pragma unroll
                        for (int b = 0; b < 8; b++) s_rsR[b][o] = hs[b];
                    } else {
                        const int ir = (jp - 512) >> 4;
#pragma unroll
                        for (int b = 0; b < 8; b++) s_rsI[b][ir] = hs[b];
                    }
                }
            }
        }
        if (tid < 512) {
            s_tov0[ov_b][ov_g] = tanhf(fmaf(invS, accC, -g_ov0base[ov_g]));
            // stage next step's x-part into the OTHER buffer (no conflict with
            // this step's GEMM reads; next GEMM is 3 barriers away)
            if (fb_k < 32 && t + 1 < T_STEPS)
                s_featX[(t + 1) & 1][fb_k][fb_b] = make_float2(rx, rx);
        }
        __syncthreads();                         // B2

        // ---- P2/P3: ov1 gemm | r-einsum | i-einsum -------------------------
        if (warp < 8) {
            const int b = warp;
            float acc = 0.f;
#pragma unroll 8
            for (int k = 0; k < 64; k++) acc += s_tov0[b][k] * g_sigWrT[k * 32 + lane];
            s_ov1[b][lane] = acc;
        } else if (warp < 16) {
            const int b = warp - 8;
            float crv = s_c[b][lane] / fmaxf(s_rsR[b][lane], 1e-12f);
            float m2 = 0.f;
#pragma unroll 8
            for (int o = 0; o < 32; o++)
                m2 = fmaf(s_P[b][o * 32 + lane], __shfl_sync(0xffffffffu, crv, o), m2);
            s_m2[b][lane] = m2;
        } else {
            const int wloc = warp - 16;
#pragma unroll
            for (int bb2 = 0; bb2 < 2; bb2++) {
                const int b = wloc * 2 + bb2;
                float m1 = 0.f;
#pragma unroll
                for (int ii = 0; ii < 4; ii++) {
                    float sc = sfX[ii * 8 + b].x / fmaxf(s_rsI[b][ii], 1e-12f);
                    m1 = fmaf(s_I[b][ii * 32 + lane], sc, m1);
                }
                s_m1[b][lane] = m1;
            }
        }
        __syncthreads();                         // B3

        // ---- P4: combine, MR gate, LN, outputs, new carry (+c-feat) --------
        if (warp < 8) {
            const int b = warp;
            float mn = s_m1[b][lane] + s_m2[b][lane];
            float o  = s_go[b][lane];
            float f  = 1.f - o;
            float x  = s_ov1[b][lane];
            float mu = wsum32(x) * (1.f / 32.f);
            float d  = x - mu;
            float var = wsum32(d * d) * (1.f / 32.f);
            float ln  = d * rsqrtf(var + 1e-5f) * r_lng + r_lnb;
            float ov2 = ln - fmaxf(ln - f, 0.f);
            float MR  = fmaxf(ov2 + 1.f - f, 0.f) + f - 1.f;
            float op  = o + MR;
            float h   = o * mn;
            float cn  = (1.f - op) * mn;
            float mf  = MR * mn;
            size_t idx = (size_t)t * BATCH * OUTDIM + (size_t)(cta * BC + b) * OUTDIM + lane;
            out_h[idx] = h;  out_c[idx] = cn; out_o[idx] = o;  out_mr[idx] = MR;
            out_op[idx] = op; out_mf[idx] = mf; out_of[idx] = h;
            s_c[b][lane] = cn;
            s_featC[lane][b] = make_float2(cn, cn);   // c-part feat for t+1
            float as = wsum32(fabsf(cn));
            if (lane == 0) s_abs[b] = as;
        }
        __syncthreads();                         // B4
        // post this CTA's |c_new| partial for step t+1 (tag+value, one store)
        if (tid == 0) {
            float p = 0.f;
#pragma unroll
            for (int b = 0; b < 8; b++) p += s_abs[b];
            ull pk = ((ull)(unsigned)(t + 2) << 32) | (ull)__float_as_uint(p);
            post_slot(g_slot + (size_t)(t + 1) * NCTA + cta, pk);
        }
    }
}

// ---------------- launch ------------------------------------------------------
extern "C" void kernel_launch(void* const* d_in, const int* in_sizes, int n_in,
                              void* d_out, int out_size) {
    const float* xm  = (const float*)d_in[0];
    const float* xa  = (const float*)d_in[1];
    const float* Wi  = (const float*)d_in[2];
    const float* bi  = (const float*)d_in[3];
    const float* Wr  = (const float*)d_in[4];
    const float* br  = (const float*)d_in[5];
    const float* Wo  = (const float*)d_in[6];
    const float* bo  = (const float*)d_in[7];
    const float* Ws  = (const float*)d_in[8];
    const float* Wrm = (const float*)d_in[9];
    const float* b0  = (const float*)d_in[10];
    const float* lng = (const float*)d_in[11];
    const float* lnb = (const float*)d_in[12];
    (void)in_sizes; (void)n_in; (void)out_size;

    prep_kernel<<<128, 256>>>(Wi, bi, Wr, br, Wo, bo, Ws, Wrm, b0);
    lstm_kernel<<<NCTA, NTHREADS>>>(xm, xa, lng, lnb, (float*)d_out);
}

// round 13
// speedup vs baseline: 1.6447x; 1.6447x over previous
#include <cuda_runtime.h>
#include <cstdint>

#define T_STEPS 512
#define BATCH   512
#define INDIM   4
#define AUXDIM  28
#define OUTDIM  32
#define GDIM    64
#define NCTA    64
#define BC      8          // batch rows per CTA
#define NTHREADS 640
#define JCOLS   1184       // 1024 (W_r) | 128 (W_i) | 32 (W_o)
#define JPAIRS  592
#define CACHED_JP 288      // jp < 288 -> caching loads (576 cols = 147KB, L1-resident)

typedef unsigned long long ull;

// ---------------- device globals (scratch; no allocation allowed) -------------
__device__ __align__(16) float g_W[64 * JCOLS];  // [k][j] transposed packed weights
__device__ float g_bias[JCOLS];
__device__ float g_expWs[32 * 64];         // exp(W_s)[o][g]
__device__ float g_ov0base[64];            // sum_o b0[o]*exp(W_s)[o][g]
__device__ float g_sigWrT[64 * 32];        // sigmoid(W_rm^T)[k][j]
__device__ __align__(16) ull g_slot[(T_STEPS + 1) * NCTA];  // (tag<<32)|float-bits

__device__ __forceinline__ void ffma2(ull &d, ull a, ull b) {
    asm volatile("fma.rn.f32x2 %0, %1, %2, %0;" : "+l"(d) : "l"(a), "l"(b));
}
__device__ __forceinline__ float wsum32(float v) {
#pragma unroll
    for (int s = 16; s; s >>= 1) v += __shfl_xor_sync(0xffffffffu, v, s);
    return v;
}
__device__ __forceinline__ float sigmoidf_(float x) { return 1.f / (1.f + expf(-x)); }

// Morally-strong relaxed gpu-scope handshake (single 8B word carries tag+value:
// strong ops are single-copy atomic + coherently visible; no fence, no L1 flush).
// Backoff polling: the handshake has one full step of slack (step t consumes
// posts issued at the end of step t-1), so the common path is a SINGLE load.
// Only on a miss do we nanosleep-retry -- this removes the continuous
// chip-wide strong-load spin (L2 hot-spot + power/DVFS pressure) of round 11.
__device__ __forceinline__ float wait_slot(const ull* p, unsigned tag) {
    ull v;
    asm volatile("ld.relaxed.gpu.global.u64 %0, [%1];"
                 : "=l"(v) : "l"(p) : "memory");
    while ((unsigned)(v >> 32) != tag) {
        __nanosleep(256);
        asm volatile("ld.relaxed.gpu.global.u64 %0, [%1];"
                     : "=l"(v) : "l"(p) : "memory");
    }
    return __uint_as_float((unsigned)v);
}
__device__ __forceinline__ void post_slot(ull* p, ull pk) {
    asm volatile("st.relaxed.gpu.global.u64 [%0], %1;"
                 :: "l"(p), "l"(pk) : "memory");
}

// ---------------- prep kernel: transpose/pack weights, reset sync state -------
__global__ void prep_kernel(const float* __restrict__ Wi, const float* __restrict__ bi,
                            const float* __restrict__ Wr, const float* __restrict__ br,
                            const float* __restrict__ Wo, const float* __restrict__ bo,
                            const float* __restrict__ Ws, const float* __restrict__ Wrm,
                            const float* __restrict__ b0) {
    int idx = blockIdx.x * blockDim.x + threadIdx.x;
    int stride = gridDim.x * blockDim.x;
    for (int i = idx; i < 64 * JCOLS; i += stride) {
        int k = i / JCOLS, j = i % JCOLS;
        float v;
        if (j < 1024)       v = Wr[j * 64 + k];
        else if (j < 1152)  v = Wi[(j - 1024) * 64 + k];
        else                v = Wo[(j - 1152) * 64 + k];
        g_W[k * JCOLS + j] = v;
    }
    for (int j = idx; j < JCOLS; j += stride)
        g_bias[j] = (j < 1024) ? br[j] : ((j < 1152) ? bi[j - 1024] : bo[j - 1152]);
    for (int i = idx; i < 32 * 64; i += stride) g_expWs[i] = expf(Ws[i]);
    for (int i = idx; i < 64 * 32; i += stride) {
        int k = i / 32, j = i % 32;
        g_sigWrT[i] = 1.f / (1.f + expf(-Wrm[j * 64 + k]));
    }
    for (int g = idx; g < 64; g += stride) {
        float s = 0.f;
        for (int o = 0; o < 32; o++) s += b0[o] * expf(Ws[o * 64 + g]);
        g_ov0base[g] = s;
    }
    // reset ALL slots (stale tags from a previous graph replay would alias),
    // then arm step 0 with partial |c| = 0, tag = 1.
    for (int i = idx; i < (T_STEPS + 1) * NCTA; i += stride) g_slot[i] = 0ull;
    for (int i = idx; i < NCTA; i += stride) g_slot[i] = (1ull << 32);
}

// ---------------- GEMM inner loop (col-pair f32x2, dup'd feat) ----------------
template<bool CG>
__device__ __forceinline__ void run_gemm(const float* __restrict__ wcol,
                                         const float2* __restrict__ sfX,
                                         const float2* __restrict__ sfC,
                                         ull accA[8], ull accB[8]) {
#pragma unroll 8
    for (int k = 0; k < 32; k++) {
        const float* p = wcol + k * JCOLS;
        ull w = CG ? __ldcg((const ull*)p) : *(const ull*)p;
        const longlong2* f = (const longlong2*)(sfX + k * 8);
        longlong2 f01 = f[0], f23 = f[1], f45 = f[2], f67 = f[3];
        ffma2(accA[0], w, (ull)f01.x); ffma2(accA[1], w, (ull)f01.y);
        ffma2(accA[2], w, (ull)f23.x); ffma2(accA[3], w, (ull)f23.y);
        ffma2(accA[4], w, (ull)f45.x); ffma2(accA[5], w, (ull)f45.y);
        ffma2(accA[6], w, (ull)f67.x); ffma2(accA[7], w, (ull)f67.y);
    }
#pragma unroll 8
    for (int k = 0; k < 32; k++) {
        const float* p = wcol + (k + 32) * JCOLS;
        ull w = CG ? __ldcg((const ull*)p) : *(const ull*)p;
        const longlong2* f = (const longlong2*)(sfC + k * 8);
        longlong2 f01 = f[0], f23 = f[1], f45 = f[2], f67 = f[3];
        ffma2(accB[0], w, (ull)f01.x); ffma2(accB[1], w, (ull)f01.y);
        ffma2(accB[2], w, (ull)f23.x); ffma2(accB[3], w, (ull)f23.y);
        ffma2(accB[4], w, (ull)f45.x); ffma2(accB[5], w, (ull)f45.y);
        ffma2(accB[6], w, (ull)f67.x); ffma2(accB[7], w, (ull)f67.y);
    }
}

// ---------------- persistent recurrent kernel --------------------------------
__global__ void __launch_bounds__(NTHREADS, 1) lstm_kernel(
    const float* __restrict__ xm, const float* __restrict__ xa,
    const float* __restrict__ lng, const float* __restrict__ lnb,
    float* __restrict__ out) {
    __shared__ __align__(16) float2 s_featX[2][32][8];  // x-part, double-buffered
    __shared__ __align__(16) float2 s_featC[32][8];     // c-part (raw carry, dup)
    __shared__ float s_c[8][32];
    __shared__ float s_P[8][1024];
    __shared__ float s_I[8][128];
    __shared__ float s_go[8][32];
    __shared__ float s_tov0[8][64];
    __shared__ float s_ov1[8][32];
    __shared__ float s_m1[8][32];
    __shared__ float s_m2[8][32];
    __shared__ float s_rsR[8][32];
    __shared__ float s_rsI[8][4];
    __shared__ float s_abs[8];
    __shared__ float s_invS;

    const int tid  = threadIdx.x;
    const int cta  = blockIdx.x;
    const int lane = tid & 31;
    const int warp = tid >> 5;

    const int  jp = tid;
    const bool gemm_active = (jp < JPAIRS);
    const float* wcol = g_W + 2 * jp;
    float bias0 = 0.f, bias1 = 0.f;
    if (gemm_active) { bias0 = g_bias[2 * jp]; bias1 = g_bias[2 * jp + 1]; }

    const int fb_k = tid >> 3, fb_b = tid & 7;   // feat build (tid<512)
    const int ov_b = tid >> 6, ov_g = tid & 63;  // ov0 raw    (tid<512)

    float r_lng = 0.f, r_lnb = 0.f;
    if (warp < 8) { r_lng = lng[lane]; r_lnb = lnb[lane]; }

    // init: zero carry state, preload x for t=0, build initial feat buffers
    for (int i = tid; i < 8 * 32; i += NTHREADS) ((float*)s_c)[i] = 0.f;
    for (int i = tid; i < 32 * 8; i += NTHREADS)
        ((float2*)s_featC)[i] = make_float2(0.f, 0.f);
    float rx = 0.f;
    const int gb = cta * BC + fb_b;
    if (tid < 512 && fb_k < 32) {
        rx = (fb_k < INDIM) ? xm[(size_t)gb * INDIM + fb_k]
                            : xa[(size_t)gb * AUXDIM + (fb_k - INDIM)];
        s_featX[0][fb_k][fb_b] = make_float2(rx, rx);
    }

    const size_t OSZ = (size_t)T_STEPS * BATCH * OUTDIM;
    float* out_h  = out;
    float* out_c  = out + OSZ;
    float* out_o  = out + 2 * OSZ;
    float* out_mr = out + 3 * OSZ;
    float* out_op = out + 4 * OSZ;
    float* out_mf = out + 5 * OSZ;
    float* out_of = out + 6 * OSZ;

    __syncthreads();

    for (int t = 0; t < T_STEPS; t++) {
        const float2* sfX = &s_featX[t & 1][0][0];

        // ---- GEMM phase (no P0: feat was staged by prior epilogue/P4) -----
        ull accA[8], accB[8];
        if (gemm_active) {
#pragma unroll
            for (int b = 0; b < 8; b++) { accA[b] = 0ull; accB[b] = 0ull; }
            if (jp < CACHED_JP) run_gemm<false>(wcol, sfX, &s_featC[0][0], accA, accB);
            else                run_gemm<true >(wcol, sfX, &s_featC[0][0], accA, accB);
        }
        // ov0 raw: c @ exp(W_s)  (one output per thread, tid<512)
        float accC = 0.f;
        if (tid < 512) {
#pragma unroll 8
            for (int o = 0; o < 32; o++) accC += s_c[ov_b][o] * g_expWs[o * 64 + ov_g];
        }
        // prefetch next step's x into rx (consumed by this step's epilogue)
        if (tid < 512 && fb_k < 32 && t + 1 < T_STEPS) {
            rx = (fb_k < INDIM)
                     ? xm[(size_t)(t + 1) * BATCH * INDIM + (size_t)gb * INDIM + fb_k]
                     : xa[(size_t)(t + 1) * BATCH * AUXDIM + (size_t)gb * AUXDIM + (fb_k - INDIM)];
        }
        // warp 19 (idle in GEMM): handshake overlaps the GEMM; backoff polling
        if (warp == 19) {
            const unsigned tag = (unsigned)(t + 1);
            const ull* base = g_slot + (size_t)t * NCTA;
            float p0 = wait_slot(base + lane, tag);
            float p1 = wait_slot(base + lane + 32, tag);
            float v = wsum32(p0 + p1);
            if (lane == 0) s_invS = 1.f / (v + 1e-5f);
        }
        __syncthreads();                         // B1: invS visible; GEMM reads done
        const float invS = s_invS;

        // ---- Epilogue: logits, activations, fused row-sums; stage next x ---
        if (gemm_active) {
            const int j0 = 2 * jp;
            float hs[8];
#pragma unroll
            for (int b = 0; b < 8; b++) {
                float2 a  = *(float2*)&accA[b];
                float2 bb = *(float2*)&accB[b];
                float v0 = fmaf(invS, bb.x, a.x) + bias0;
                float v1 = fmaf(invS, bb.y, a.y) + bias1;
                if (jp < 512) {                       // W_r: relu
                    v0 = fmaxf(v0, 0.f); v1 = fmaxf(v1, 0.f);
                    *(float2*)&s_P[b][j0] = make_float2(v0, v1);
                    hs[b] = v0 + v1;
                } else if (jp < 576) {                // W_i: sigmoid
                    v0 = sigmoidf_(v0); v1 = sigmoidf_(v1);
                    *(float2*)&s_I[b][j0 - 1024] = make_float2(v0, v1);
                    hs[b] = v0 + v1;
                } else {                              // W_o: sigmoid
                    *(float2*)&s_go[b][j0 - 1152] =
                        make_float2(sigmoidf_(v0), sigmoidf_(v1));
                }
            }
            if (jp < 576) {   // 16-lane row-sum: 16 consecutive threads = one row
#pragma unroll
                for (int b = 0; b < 8; b++) {
#pragma unroll
                    for (int s = 1; s < 16; s <<= 1)
                        hs[b] += __shfl_xor_sync(0xffffffffu, hs[b], s);
                }
                if ((jp & 15) == 0) {
                    if (jp < 512) {
                        const int o = jp >> 4;
#pragma unroll
                        for (int b = 0; b < 8; b++) s_rsR[b][o] = hs[b];
                    } else {
                        const int ir = (jp - 512) >> 4;
#pragma unroll
                        for (int b = 0; b < 8; b++) s_rsI[b][ir] = hs[b];
                    }
                }
            }
        }
        if (tid < 512) {
            s_tov0[ov_b][ov_g] = tanhf(fmaf(invS, accC, -g_ov0base[ov_g]));
            // stage next step's x-part into the OTHER buffer (no conflict with
            // this step's GEMM reads; next GEMM is 3 barriers away)
            if (fb_k < 32 && t + 1 < T_STEPS)
                s_featX[(t + 1) & 1][fb_k][fb_b] = make_float2(rx, rx);
        }
        __syncthreads();                         // B2

        // ---- P2/P3: ov1 gemm | r-einsum | i-einsum -------------------------
        if (warp < 8) {
            const int b = warp;
            float acc = 0.f;
#pragma unroll 8
            for (int k = 0; k < 64; k++) acc += s_tov0[b][k] * g_sigWrT[k * 32 + lane];
            s_ov1[b][lane] = acc;
        } else if (warp < 16) {
            const int b = warp - 8;
            float crv = s_c[b][lane] / fmaxf(s_rsR[b][lane], 1e-12f);
            float m2 = 0.f;
#pragma unroll 8
            for (int o = 0; o < 32; o++)
                m2 = fmaf(s_P[b][o * 32 + lane], __shfl_sync(0xffffffffu, crv, o), m2);
            s_m2[b][lane] = m2;
        } else {
            const int wloc = warp - 16;
#pragma unroll
            for (int bb2 = 0; bb2 < 2; bb2++) {
                const int b = wloc * 2 + bb2;
                float m1 = 0.f;
#pragma unroll
                for (int ii = 0; ii < 4; ii++) {
                    float sc = sfX[ii * 8 + b].x / fmaxf(s_rsI[b][ii], 1e-12f);
                    m1 = fmaf(s_I[b][ii * 32 + lane], sc, m1);
                }
                s_m1[b][lane] = m1;
            }
        }
        __syncthreads();                         // B3

        // ---- P4: combine, MR gate, LN, outputs, new carry (+c-feat) --------
        if (warp < 8) {
            const int b = warp;
            float mn = s_m1[b][lane] + s_m2[b][lane];
            float o  = s_go[b][lane];
            float f  = 1.f - o;
            float x  = s_ov1[b][lane];
            float mu = wsum32(x) * (1.f / 32.f);
            float d  = x - mu;
            float var = wsum32(d * d) * (1.f / 32.f);
            float ln  = d * rsqrtf(var + 1e-5f) * r_lng + r_lnb;
            float ov2 = ln - fmaxf(ln - f, 0.f);
            float MR  = fmaxf(ov2 + 1.f - f, 0.f) + f - 1.f;
            float op  = o + MR;
            float h   = o * mn;
            float cn  = (1.f - op) * mn;
            float mf  = MR * mn;
            size_t idx = (size_t)t * BATCH * OUTDIM + (size_t)(cta * BC + b) * OUTDIM + lane;
            out_h[idx] = h;  out_c[idx] = cn; out_o[idx] = o;  out_mr[idx] = MR;
            out_op[idx] = op; out_mf[idx] = mf; out_of[idx] = h;
            s_c[b][lane] = cn;
            s_featC[lane][b] = make_float2(cn, cn);   // c-part feat for t+1
            float as = wsum32(fabsf(cn));
            if (lane == 0) s_abs[b] = as;
        }
        __syncthreads();                         // B4
        // post this CTA's |c_new| partial for step t+1 (tag+value, one store)
        if (tid == 0) {
            float p = 0.f;
#pragma unroll
            for (int b = 0; b < 8; b++) p += s_abs[b];
            ull pk = ((ull)(unsigned)(t + 2) << 32) | (ull)__float_as_uint(p);
            post_slot(g_slot + (size_t)(t + 1) * NCTA + cta, pk);
        }
    }
}

// ---------------- launch ------------------------------------------------------
extern "C" void kernel_launch(void* const* d_in, const int* in_sizes, int n_in,
                              void* d_out, int out_size) {
    const float* xm  = (const float*)d_in[0];
    const float* xa  = (const float*)d_in[1];
    const float* Wi  = (const float*)d_in[2];
    const float* bi  = (const float*)d_in[3];
    const float* Wr  = (const float*)d_in[4];
    const float* br  = (const float*)d_in[5];
    const float* Wo  = (const float*)d_in[6];
    const float* bo  = (const float*)d_in[7];
    const float* Ws  = (const float*)d_in[8];
    const float* Wrm = (const float*)d_in[9];
    const float* b0  = (const float*)d_in[10];
    const float* lng = (const float*)d_in[11];
    const float* lnb = (const float*)d_in[12];
    (void)in_sizes; (void)n_in; (void)out_size;

    prep_kernel<<<128, 256>>>(Wi, bi, Wr, br, Wo, bo, Ws, Wrm, b0);
    lstm_kernel<<<NCTA, NTHREADS>>>(xm, xa, lng, lnb, (float*)d_out);
}

// round 14
// speedup vs baseline: 2.4746x; 1.5046x over previous
#include <cuda_runtime.h>
#include <cstdint>

#define T_STEPS 512
#define BATCH   512
#define INDIM   4
#define AUXDIM  28
#define OUTDIM  32
#define GDIM    64
#define NCTA    128
#define BC      4          // batch rows per CTA
#define NTHREADS 640
#define JCOLS   1184       // 1024 (W_r) | 128 (W_i) | 32 (W_o)
#define JPAIRS  592
#define CACHED_JP 288      // jp < 288 -> caching loads (576 cols = 147KB, L1-resident)

typedef unsigned long long ull;

// ---------------- device globals (scratch; no allocation allowed) -------------
__device__ __align__(16) float g_W[64 * JCOLS];  // [k][j] transposed packed weights
__device__ float g_bias[JCOLS];
__device__ float g_expWs[32 * 64];         // exp(W_s)[o][g]
__device__ float g_ov0base[64];            // sum_o b0[o]*exp(W_s)[o][g]
__device__ float g_sigWrT[64 * 32];        // sigmoid(W_rm^T)[k][j]
__device__ __align__(16) ull g_slot[(T_STEPS + 1) * NCTA];  // (tag<<32)|float-bits

__device__ __forceinline__ void ffma2(ull &d, ull a, ull b) {
    asm volatile("fma.rn.f32x2 %0, %1, %2, %0;" : "+l"(d) : "l"(a), "l"(b));
}
__device__ __forceinline__ float wsum32(float v) {
#pragma unroll
    for (int s = 16; s; s >>= 1) v += __shfl_xor_sync(0xffffffffu, v, s);
    return v;
}
__device__ __forceinline__ float sigmoidf_(float x) { return 1.f / (1.f + expf(-x)); }

// Morally-strong relaxed gpu-scope handshake with nanosleep backoff
// (single 8B word carries tag+value; no fence, no L1 flush; no continuous spin).
__device__ __forceinline__ float wait_slot(const ull* p, unsigned tag) {
    ull v;
    asm volatile("ld.relaxed.gpu.global.u64 %0, [%1];"
                 : "=l"(v) : "l"(p) : "memory");
    while ((unsigned)(v >> 32) != tag) {
        __nanosleep(256);
        asm volatile("ld.relaxed.gpu.global.u64 %0, [%1];"
                     : "=l"(v) : "l"(p) : "memory");
    }
    return __uint_as_float((unsigned)v);
}
__device__ __forceinline__ void post_slot(ull* p, ull pk) {
    asm volatile("st.relaxed.gpu.global.u64 [%0], %1;"
                 :: "l"(p), "l"(pk) : "memory");
}

// ---------------- prep kernel: transpose/pack weights, reset sync state -------
__global__ void prep_kernel(const float* __restrict__ Wi, const float* __restrict__ bi,
                            const float* __restrict__ Wr, const float* __restrict__ br,
                            const float* __restrict__ Wo, const float* __restrict__ bo,
                            const float* __restrict__ Ws, const float* __restrict__ Wrm,
                            const float* __restrict__ b0) {
    int idx = blockIdx.x * blockDim.x + threadIdx.x;
    int stride = gridDim.x * blockDim.x;
    for (int i = idx; i < 64 * JCOLS; i += stride) {
        int k = i / JCOLS, j = i % JCOLS;
        float v;
        if (j < 1024)       v = Wr[j * 64 + k];
        else if (j < 1152)  v = Wi[(j - 1024) * 64 + k];
        else                v = Wo[(j - 1152) * 64 + k];
        g_W[k * JCOLS + j] = v;
    }
    for (int j = idx; j < JCOLS; j += stride)
        g_bias[j] = (j < 1024) ? br[j] : ((j < 1152) ? bi[j - 1024] : bo[j - 1152]);
    for (int i = idx; i < 32 * 64; i += stride) g_expWs[i] = expf(Ws[i]);
    for (int i = idx; i < 64 * 32; i += stride) {
        int k = i / 32, j = i % 32;
        g_sigWrT[i] = 1.f / (1.f + expf(-Wrm[j * 64 + k]));
    }
    for (int g = idx; g < 64; g += stride) {
        float s = 0.f;
        for (int o = 0; o < 32; o++) s += b0[o] * expf(Ws[o * 64 + g]);
        g_ov0base[g] = s;
    }
    // reset ALL slots (stale tags from a previous graph replay would alias),
    // then arm step 0 with partial |c| = 0, tag = 1.
    for (int i = idx; i < (T_STEPS + 1) * NCTA; i += stride) g_slot[i] = 0ull;
    for (int i = idx; i < NCTA; i += stride) g_slot[i] = (1ull << 32);
}

// ---------------- GEMM inner loop (col-pair f32x2, dup'd feat, BC=4) ----------
template<bool CG>
__device__ __forceinline__ void run_gemm(const float* __restrict__ wcol,
                                         const float2* __restrict__ sfX,
                                         const float2* __restrict__ sfC,
                                         ull accA[4], ull accB[4]) {
#pragma unroll 8
    for (int k = 0; k < 32; k++) {
        const float* p = wcol + k * JCOLS;
        ull w = CG ? __ldcg((const ull*)p) : *(const ull*)p;
        const longlong2* f = (const longlong2*)(sfX + k * 4);
        longlong2 f01 = f[0], f23 = f[1];
        ffma2(accA[0], w, (ull)f01.x); ffma2(accA[1], w, (ull)f01.y);
        ffma2(accA[2], w, (ull)f23.x); ffma2(accA[3], w, (ull)f23.y);
    }
#pragma unroll 8
    for (int k = 0; k < 32; k++) {
        const float* p = wcol + (k + 32) * JCOLS;
        ull w = CG ? __ldcg((const ull*)p) : *(const ull*)p;
        const longlong2* f = (const longlong2*)(sfC + k * 4);
        longlong2 f01 = f[0], f23 = f[1];
        ffma2(accB[0], w, (ull)f01.x); ffma2(accB[1], w, (ull)f01.y);
        ffma2(accB[2], w, (ull)f23.x); ffma2(accB[3], w, (ull)f23.y);
    }
}

// ---------------- persistent recurrent kernel --------------------------------
__global__ void __launch_bounds__(NTHREADS, 1) lstm_kernel(
    const float* __restrict__ xm, const float* __restrict__ xa,
    const float* __restrict__ lng, const float* __restrict__ lnb,
    float* __restrict__ out) {
    __shared__ __align__(16) float2 s_featX[2][32][BC];  // x-part, double-buffered
    __shared__ __align__(16) float2 s_featC[32][BC];     // c-part (raw carry, dup)
    __shared__ float s_c[BC][32];
    __shared__ float s_P[BC][1024];
    __shared__ float s_I[BC][128];
    __shared__ float s_go[BC][32];
    __shared__ float s_tov0[BC][64];
    __shared__ float s_ov1[BC][32];
    __shared__ float s_m1[BC][32];
    __shared__ float s_m2[BC][32];
    __shared__ float s_rsR[BC][32];
    __shared__ float s_rsI[BC][4];
    __shared__ float s_abs[BC];
    __shared__ float s_invS;

    const int tid  = threadIdx.x;
    const int cta  = blockIdx.x;
    const int lane = tid & 31;
    const int warp = tid >> 5;

    const int  jp = tid;
    const bool gemm_active = (jp < JPAIRS);
    const float* wcol = g_W + 2 * jp;
    float bias0 = 0.f, bias1 = 0.f;
    if (gemm_active) { bias0 = g_bias[2 * jp]; bias1 = g_bias[2 * jp + 1]; }

    const int fb_k = tid >> 2, fb_b = tid & 3;   // feat build (tid<128)
    const int ov_b = tid >> 6, ov_g = tid & 63;  // ov0 raw    (tid<256)

    float r_lng = 0.f, r_lnb = 0.f;
    if (warp < BC) { r_lng = lng[lane]; r_lnb = lnb[lane]; }

    // init: zero carry state, preload x for t=0, build initial feat buffers
    for (int i = tid; i < BC * 32; i += NTHREADS) ((float*)s_c)[i] = 0.f;
    for (int i = tid; i < 32 * BC; i += NTHREADS)
        ((float2*)s_featC)[i] = make_float2(0.f, 0.f);
    float rx = 0.f;
    const int gb = cta * BC + fb_b;
    if (tid < 128) {
        rx = (fb_k < INDIM) ? xm[(size_t)gb * INDIM + fb_k]
                            : xa[(size_t)gb * AUXDIM + (fb_k - INDIM)];
        s_featX[0][fb_k][fb_b] = make_float2(rx, rx);
    }

    const size_t OSZ = (size_t)T_STEPS * BATCH * OUTDIM;
    float* out_h  = out;
    float* out_c  = out + OSZ;
    float* out_o  = out + 2 * OSZ;
    float* out_mr = out + 3 * OSZ;
    float* out_op = out + 4 * OSZ;
    float* out_mf = out + 5 * OSZ;
    float* out_of = out + 6 * OSZ;

    __syncthreads();

    for (int t = 0; t < T_STEPS; t++) {
        const float2* sfX = &s_featX[t & 1][0][0];

        // ---- GEMM phase (no P0: feat staged by prior epilogue/P4) ---------
        ull accA[4], accB[4];
        if (gemm_active) {
#pragma unroll
            for (int b = 0; b < 4; b++) { accA[b] = 0ull; accB[b] = 0ull; }
            if (jp < CACHED_JP) run_gemm<false>(wcol, sfX, &s_featC[0][0], accA, accB);
            else                run_gemm<true >(wcol, sfX, &s_featC[0][0], accA, accB);
        }
        // ov0 raw: c @ exp(W_s)  (one output per thread, tid<256)
        float accC = 0.f;
        if (tid < 256) {
#pragma unroll 8
            for (int o = 0; o < 32; o++) accC += s_c[ov_b][o] * g_expWs[o * 64 + ov_g];
        }
        // prefetch next step's x into rx (consumed by this step's epilogue)
        if (tid < 128 && t + 1 < T_STEPS) {
            rx = (fb_k < INDIM)
                     ? xm[(size_t)(t + 1) * BATCH * INDIM + (size_t)gb * INDIM + fb_k]
                     : xa[(size_t)(t + 1) * BATCH * AUXDIM + (size_t)gb * AUXDIM + (fb_k - INDIM)];
        }
        // warp 19 (idle in GEMM): handshake overlaps the GEMM; backoff polling
        if (warp == 19) {
            const unsigned tag = (unsigned)(t + 1);
            const ull* base = g_slot + (size_t)t * NCTA;
            float p0 = wait_slot(base + lane, tag);
            float p1 = wait_slot(base + lane + 32, tag);
            float p2 = wait_slot(base + lane + 64, tag);
            float p3 = wait_slot(base + lane + 96, tag);
            float v = wsum32((p0 + p1) + (p2 + p3));
            if (lane == 0) s_invS = 1.f / (v + 1e-5f);
        }
        __syncthreads();                         // B1: invS visible; GEMM reads done
        const float invS = s_invS;

        // ---- Epilogue: logits, activations, fused row-sums; stage next x ---
        if (gemm_active) {
            const int j0 = 2 * jp;
            float hs[4];
#pragma unroll
            for (int b = 0; b < 4; b++) {
                float2 a  = *(float2*)&accA[b];
                float2 bb = *(float2*)&accB[b];
                float v0 = fmaf(invS, bb.x, a.x) + bias0;
                float v1 = fmaf(invS, bb.y, a.y) + bias1;
                if (jp < 512) {                       // W_r: relu
                    v0 = fmaxf(v0, 0.f); v1 = fmaxf(v1, 0.f);
                    *(float2*)&s_P[b][j0] = make_float2(v0, v1);
                    hs[b] = v0 + v1;
                } else if (jp < 576) {                // W_i: sigmoid
                    v0 = sigmoidf_(v0); v1 = sigmoidf_(v1);
                    *(float2*)&s_I[b][j0 - 1024] = make_float2(v0, v1);
                    hs[b] = v0 + v1;
                } else {                              // W_o: sigmoid
                    *(float2*)&s_go[b][j0 - 1152] =
                        make_float2(sigmoidf_(v0), sigmoidf_(v1));
                }
            }
            if (jp < 576) {   // 16-lane row-sum: 16 consecutive threads = one row
#pragma unroll
                for (int b = 0; b < 4; b++) {
#pragma unroll
                    for (int s = 1; s < 16; s <<= 1)
                        hs[b] += __shfl_xor_sync(0xffffffffu, hs[b], s);
                }
                if ((jp & 15) == 0) {
                    if (jp < 512) {
                        const int o = jp >> 4;
#pragma unroll
                        for (int b = 0; b < 4; b++) s_rsR[b][o] = hs[b];
                    } else {
                        const int ir = (jp - 512) >> 4;
#pragma unroll
                        for (int b = 0; b < 4; b++) s_rsI[b][ir] = hs[b];
                    }
                }
            }
        }
        if (tid < 256)
            s_tov0[ov_b][ov_g] = tanhf(fmaf(invS, accC, -g_ov0base[ov_g]));
        if (tid < 128 && t + 1 < T_STEPS)
            s_featX[(t + 1) & 1][fb_k][fb_b] = make_float2(rx, rx);
        __syncthreads();                         // B2

        // ---- P2/P3: ov1 gemm | r-einsum | i-einsum -------------------------
        if (warp < BC) {
            const int b = warp;
            float acc = 0.f;
#pragma unroll 8
            for (int k = 0; k < 64; k++) acc += s_tov0[b][k] * g_sigWrT[k * 32 + lane];
            s_ov1[b][lane] = acc;
        } else if (warp >= 8 && warp < 8 + BC) {
            const int b = warp - 8;
            float crv = s_c[b][lane] / fmaxf(s_rsR[b][lane], 1e-12f);
            float m2 = 0.f;
#pragma unroll 8
            for (int o = 0; o < 32; o++)
                m2 = fmaf(s_P[b][o * 32 + lane], __shfl_sync(0xffffffffu, crv, o), m2);
            s_m2[b][lane] = m2;
        } else if (warp >= 16 && warp < 18) {
            const int wloc = warp - 16;
#pragma unroll
            for (int bb2 = 0; bb2 < 2; bb2++) {
                const int b = wloc * 2 + bb2;
                float m1 = 0.f;
#pragma unroll
                for (int ii = 0; ii < 4; ii++) {
                    float sc = sfX[ii * BC + b].x / fmaxf(s_rsI[b][ii], 1e-12f);
                    m1 = fmaf(s_I[b][ii * 32 + lane], sc, m1);
                }
                s_m1[b][lane] = m1;
            }
        }
        __syncthreads();                         // B3

        // ---- P4: combine, MR gate, LN, outputs, new carry (+c-feat) --------
        if (warp < BC) {
            const int b = warp;
            float mn = s_m1[b][lane] + s_m2[b][lane];
            float o  = s_go[b][lane];
            float f  = 1.f - o;
            float x  = s_ov1[b][lane];
            float mu = wsum32(x) * (1.f / 32.f);
            float d  = x - mu;
            float var = wsum32(d * d) * (1.f / 32.f);
            float ln  = d * rsqrtf(var + 1e-5f) * r_lng + r_lnb;
            float ov2 = ln - fmaxf(ln - f, 0.f);
            float MR  = fmaxf(ov2 + 1.f - f, 0.f) + f - 1.f;
            float op  = o + MR;
            float h   = o * mn;
            float cn  = (1.f - op) * mn;
            float mf  = MR * mn;
            size_t idx = (size_t)t * BATCH * OUTDIM + (size_t)(cta * BC + b) * OUTDIM + lane;
            out_h[idx] = h;  out_c[idx] = cn; out_o[idx] = o;  out_mr[idx] = MR;
            out_op[idx] = op; out_mf[idx] = mf; out_of[idx] = h;
            s_c[b][lane] = cn;
            s_featC[lane][b] = make_float2(cn, cn);   // c-part feat for t+1
            float as = wsum32(fabsf(cn));
            if (lane == 0) s_abs[b] = as;
        }
        __syncthreads();                         // B4
        // post this CTA's |c_new| partial for step t+1 (tag+value, one store)
        if (tid == 0) {
            float p = 0.f;
#pragma unroll
            for (int b = 0; b < BC; b++) p += s_abs[b];
            ull pk = ((ull)(unsigned)(t + 2) << 32) | (ull)__float_as_uint(p);
            post_slot(g_slot + (size_t)(t + 1) * NCTA + cta, pk);
        }
    }
}

// ---------------- launch ------------------------------------------------------
extern "C" void kernel_launch(void* const* d_in, const int* in_sizes, int n_in,
                              void* d_out, int out_size) {
    const float* xm  = (const float*)d_in[0];
    const float* xa  = (const float*)d_in[1];
    const float* Wi  = (const float*)d_in[2];
    const float* bi  = (const float*)d_in[3];
    const float* Wr  = (const float*)d_in[4];
    const float* br  = (const float*)d_in[5];
    const float* Wo  = (const float*)d_in[6];
    const float* bo  = (const float*)d_in[7];
    const float* Ws  = (const float*)d_in[8];
    const float* Wrm = (const float*)d_in[9];
    const float* b0  = (const float*)d_in[10];
    const float* lng = (const float*)d_in[11];
    const float* lnb = (const float*)d_in[12];
    (void)in_sizes; (void)n_in; (void)out_size;

    prep_kernel<<<128, 256>>>(Wi, bi, Wr, br, Wo, bo, Ws, Wrm, b0);
    lstm_kernel<<<NCTA, NTHREADS>>>(xm, xa, lng, lnb, (float*)d_out);
}

// round 16
// speedup vs baseline: 2.6597x; 1.0748x over previous
#include <cuda_runtime.h>
#include <cstdint>

#define T_STEPS 512
#define BATCH   512
#define INDIM   4
#define AUXDIM  28
#define OUTDIM  32
#define GDIM    64
#define NCTA    128
#define BC      4          // batch rows per CTA
#define NTHREADS 640
#define JCOLS   1184       // 1024 (W_r) | 128 (W_i) | 32 (W_o)
#define JPAIRS  592
#define CACHED_JP 288      // jp < 288 -> caching loads (576 cols = 147KB, L1-resident)

typedef unsigned long long ull;

// ---------------- device globals (scratch; no allocation allowed) -------------
__device__ __align__(16) float g_W[64 * JCOLS];  // [k][j] transposed packed weights
__device__ float g_bias[JCOLS];
__device__ float g_expWs[32 * 64];         // exp(W_s)[o][g]
__device__ float g_ov0base[64];            // sum_o b0[o]*exp(W_s)[o][g]
__device__ float g_sigWrT[64 * 32];        // sigmoid(W_rm^T)[k][j]
__device__ __align__(16) ull g_slot[(T_STEPS + 1) * NCTA];  // (tag<<32)|float-bits

__device__ __forceinline__ void ffma2(ull &d, ull a, ull b) {
    asm volatile("fma.rn.f32x2 %0, %1, %2, %0;" : "+l"(d) : "l"(a), "l"(b));
}
__device__ __forceinline__ float wsum32(float v) {
#pragma unroll
    for (int s = 16; s; s >>= 1) v += __shfl_xor_sync(0xffffffffu, v, s);
    return v;
}
__device__ __forceinline__ float sigmoidf_(float x) { return 1.f / (1.f + expf(-x)); }

// Morally-strong relaxed gpu-scope handshake with nanosleep backoff
// (single 8B word carries tag+value; no fence, no L1 flush; no continuous spin).
__device__ __forceinline__ float wait_slot(const ull* p, unsigned tag) {
    ull v;
    asm volatile("ld.relaxed.gpu.global.u64 %0, [%1];"
                 : "=l"(v) : "l"(p) : "memory");
    while ((unsigned)(v >> 32) != tag) {
        __nanosleep(256);
        asm volatile("ld.relaxed.gpu.global.u64 %0, [%1];"
                     : "=l"(v) : "l"(p) : "memory");
    }
    return __uint_as_float((unsigned)v);
}
__device__ __forceinline__ void post_slot(ull* p, ull pk) {
    asm volatile("st.relaxed.gpu.global.u64 [%0], %1;"
                 :: "l"(p), "l"(pk) : "memory");
}

// ---------------- prep kernel: transpose/pack weights, reset sync state -------
__global__ void prep_kernel(const float* __restrict__ Wi, const float* __restrict__ bi,
                            const float* __restrict__ Wr, const float* __restrict__ br,
                            const float* __restrict__ Wo, const float* __restrict__ bo,
                            const float* __restrict__ Ws, const float* __restrict__ Wrm,
                            const float* __restrict__ b0) {
    int idx = blockIdx.x * blockDim.x + threadIdx.x;
    int stride = gridDim.x * blockDim.x;
    for (int i = idx; i < 64 * JCOLS; i += stride) {
        int k = i / JCOLS, j = i % JCOLS;
        float v;
        if (j < 1024)       v = Wr[j * 64 + k];
        else if (j < 1152)  v = Wi[(j - 1024) * 64 + k];
        else                v = Wo[(j - 1152) * 64 + k];
        g_W[k * JCOLS + j] = v;
    }
    for (int j = idx; j < JCOLS; j += stride)
        g_bias[j] = (j < 1024) ? br[j] : ((j < 1152) ? bi[j - 1024] : bo[j - 1152]);
    for (int i = idx; i < 32 * 64; i += stride) g_expWs[i] = expf(Ws[i]);
    for (int i = idx; i < 64 * 32; i += stride) {
        int k = i / 32, j = i % 32;
        g_sigWrT[i] = 1.f / (1.f + expf(-Wrm[j * 64 + k]));
    }
    for (int g = idx; g < 64; g += stride) {
        float s = 0.f;
        for (int o = 0; o < 32; o++) s += b0[o] * expf(Ws[o * 64 + g]);
        g_ov0base[g] = s;
    }
    // reset ALL slots (stale tags from a previous graph replay would alias),
    // then arm step 0 with partial |c| = 0, tag = 1.
    for (int i = idx; i < (T_STEPS + 1) * NCTA; i += stride) g_slot[i] = 0ull;
    for (int i = idx; i < NCTA; i += stride) g_slot[i] = (1ull << 32);
}

// ---------------- GEMM inner loop (col-pair f32x2, dup'd feat, BC=4) ----------
// Per-CTA k-chunk rotation (rot in 0..7, chunks of 4 k): de-phases the 128
// lock-step CTAs so they hit DIFFERENT weight cache lines at any instant,
// spreading demand across L2 slices instead of serializing ~128 SMs on the
// handful of lines of the current k-slice. Accumulation order changes only
// within each 32-k half, preserving the X/C invS split exactly.
template<bool CG>
__device__ __forceinline__ void run_gemm(const float* __restrict__ wcol,
                                         const float2* __restrict__ sfX,
                                         const float2* __restrict__ sfC,
                                         ull accA[4], ull accB[4], int rot) {
#pragma unroll
    for (int cc = 0; cc < 8; cc++) {
        int c = cc + rot; if (c >= 8) c -= 8;          // rotated chunk 0..7
        const float* pX = wcol + (c * 4) * JCOLS;           // k = c*4 .. c*4+3
        const float* pC = wcol + (32 + c * 4) * JCOLS;      // k = 32+c*4 ..
        const longlong2* fX = (const longlong2*)(sfX + c * 16);
        const longlong2* fC = (const longlong2*)(sfC + c * 16);
#pragma unroll
        for (int u = 0; u < 4; u++) {
            const float* p = pX + u * JCOLS;
            ull w = CG ? __ldcg((const ull*)p) : *(const ull*)p;
            longlong2 f01 = fX[u * 2], f23 = fX[u * 2 + 1];
            ffma2(accA[0], w, (ull)f01.x); ffma2(accA[1], w, (ull)f01.y);
            ffma2(accA[2], w, (ull)f23.x); ffma2(accA[3], w, (ull)f23.y);
        }
#pragma unroll
        for (int u = 0; u < 4; u++) {
            const float* p = pC + u * JCOLS;
            ull w = CG ? __ldcg((const ull*)p) : *(const ull*)p;
            longlong2 f01 = fC[u * 2], f23 = fC[u * 2 + 1];
            ffma2(accB[0], w, (ull)f01.x); ffma2(accB[1], w, (ull)f01.y);
            ffma2(accB[2], w, (ull)f23.x); ffma2(accB[3], w, (ull)f23.y);
        }
    }
}

// ---------------- persistent recurrent kernel --------------------------------
__global__ void __launch_bounds__(NTHREADS, 1) lstm_kernel(
    const float* __restrict__ xm, const float* __restrict__ xa,
    const float* __restrict__ lng, const float* __restrict__ lnb,
    float* __restrict__ out) {
    __shared__ __align__(16) float2 s_featX[2][32][BC];  // x-part, double-buffered
    __shared__ __align__(16) float2 s_featC[32][BC];     // c-part (raw carry, dup)
    __shared__ float s_c[BC][32];
    __shared__ float s_P[BC][1024];
    __shared__ float s_I[BC][128];
    __shared__ float s_go[BC][32];
    __shared__ float s_tov0[BC][64];
    __shared__ float s_ov1[BC][32];
    __shared__ float s_m1[BC][32];
    __shared__ float s_m2[BC][32];
    __shared__ float s_rsR[BC][32];
    __shared__ float s_rsI[BC][4];
    __shared__ float s_abs[BC];
    __shared__ float s_invS;

    const int tid  = threadIdx.x;
    const int cta  = blockIdx.x;
    const int lane = tid & 31;
    const int warp = tid >> 5;
    const int rot  = cta & 7;

    const int  jp = tid;
    const bool gemm_active = (jp < JPAIRS);
    const float* wcol = g_W + 2 * jp;
    float bias0 = 0.f, bias1 = 0.f;
    if (gemm_active) { bias0 = g_bias[2 * jp]; bias1 = g_bias[2 * jp + 1]; }

    const int fb_k = tid >> 2, fb_b = tid & 3;   // feat build (tid<128)
    const int ov_b = tid >> 6, ov_g = tid & 63;  // ov0 raw    (tid<256)

    float r_lng = 0.f, r_lnb = 0.f;
    if (warp < BC) { r_lng = lng[lane]; r_lnb = lnb[lane]; }

    // init: zero carry state, preload x for t=0, build initial feat buffers
    for (int i = tid; i < BC * 32; i += NTHREADS) ((float*)s_c)[i] = 0.f;
    for (int i = tid; i < 32 * BC; i += NTHREADS)
        ((float2*)s_featC)[i] = make_float2(0.f, 0.f);
    float rx = 0.f;
    const int gb = cta * BC + fb_b;
    if (tid < 128) {
        rx = (fb_k < INDIM) ? xm[(size_t)gb * INDIM + fb_k]
                            : xa[(size_t)gb * AUXDIM + (fb_k - INDIM)];
        s_featX[0][fb_k][fb_b] = make_float2(rx, rx);
    }

    const size_t OSZ = (size_t)T_STEPS * BATCH * OUTDIM;
    float* out_h  = out;
    float* out_c  = out + OSZ;
    float* out_o  = out + 2 * OSZ;
    float* out_mr = out + 3 * OSZ;
    float* out_op = out + 4 * OSZ;
    float* out_mf = out + 5 * OSZ;
    float* out_of = out + 6 * OSZ;

    __syncthreads();

    for (int t = 0; t < T_STEPS; t++) {
        const float2* sfX = &s_featX[t & 1][0][0];

        // ---- GEMM phase (no P0: feat staged by prior epilogue/P4) ---------
        ull accA[4], accB[4];
        if (gemm_active) {
#pragma unroll
            for (int b = 0; b < 4; b++) { accA[b] = 0ull; accB[b] = 0ull; }
            if (jp < CACHED_JP) run_gemm<false>(wcol, sfX, &s_featC[0][0], accA, accB, rot);
            else                run_gemm<true >(wcol, sfX, &s_featC[0][0], accA, accB, rot);
        }
        // ov0 raw: c @ exp(W_s)  (one output per thread, tid<256)
        float accC = 0.f;
        if (tid < 256) {
#pragma unroll 8
            for (int o = 0; o < 32; o++) accC += s_c[ov_b][o] * g_expWs[o * 64 + ov_g];
        }
        // prefetch next step's x into rx (consumed by this step's epilogue)
        if (tid < 128 && t + 1 < T_STEPS) {
            rx = (fb_k < INDIM)
                     ? xm[(size_t)(t + 1) * BATCH * INDIM + (size_t)gb * INDIM + fb_k]
                     : xa[(size_t)(t + 1) * BATCH * AUXDIM + (size_t)gb * AUXDIM + (fb_k - INDIM)];
        }
        // warp 19 (idle in GEMM): handshake overlaps the GEMM; backoff polling
        if (warp == 19) {
            const unsigned tag = (unsigned)(t + 1);
            const ull* base = g_slot + (size_t)t * NCTA;
            float p0 = wait_slot(base + lane, tag);
            float p1 = wait_slot(base + lane + 32, tag);
            float p2 = wait_slot(base + lane + 64, tag);
            float p3 = wait_slot(base + lane + 96, tag);
            float v = wsum32((p0 + p1) + (p2 + p3));
            if (lane == 0) s_invS = 1.f / (v + 1e-5f);
        }
        __syncthreads();                         // B1: invS visible; GEMM reads done
        const float invS = s_invS;

        // ---- Epilogue: logits, activations, fused row-sums; stage next x ---
        if (gemm_active) {
            const int j0 = 2 * jp;
            float hs[4];
#pragma unroll
            for (int b = 0; b < 4; b++) {
                float2 a  = *(float2*)&accA[b];
                float2 bb = *(float2*)&accB[b];
                float v0 = fmaf(invS, bb.x, a.x) + bias0;
                float v1 = fmaf(invS, bb.y, a.y) + bias1;
                if (jp < 512) {                       // W_r: relu
                    v0 = fmaxf(v0, 0.f); v1 = fmaxf(v1, 0.f);
                    *(float2*)&s_P[b][j0] = make_float2(v0, v1);
                    hs[b] = v0 + v1;
                } else if (jp < 576) {                // W_i: sigmoid
                    v0 = sigmoidf_(v0); v1 = sigmoidf_(v1);
                    *(float2*)&s_I[b][j0 - 1024] = make_float2(v0, v1);
                    hs[b] = v0 + v1;
                } else {                              // W_o: sigmoid
                    *(float2*)&s_go[b][j0 - 1152] =
                        make_float2(sigmoidf_(v0), sigmoidf_(v1));
                }
            }
            if (jp < 576) {   // 16-lane row-sum: 16 consecutive threads = one row
#pragma unroll
                for (int b = 0; b < 4; b++) {
#pragma unroll
                    for (int s = 1; s < 16; s <<= 1)
                        hs[b] += __shfl_xor_sync(0xffffffffu, hs[b], s);
                }
                if ((jp & 15) == 0) {
                    if (jp < 512) {
                        const int o = jp >> 4;
#pragma unroll
                        for (int b = 0; b < 4; b++) s_rsR[b][o] = hs[b];
                    } else {
                        const int ir = (jp - 512) >> 4;
#pragma unroll
                        for (int b = 0; b < 4; b++) s_rsI[b][ir] = hs[b];
                    }
                }
            }
        }
        if (tid < 256)
            s_tov0[ov_b][ov_g] = tanhf(fmaf(invS, accC, -g_ov0base[ov_g]));
        if (tid < 128 && t + 1 < T_STEPS)
            s_featX[(t + 1) & 1][fb_k][fb_b] = make_float2(rx, rx);
        __syncthreads();                         // B2

        // ---- P2/P3: ov1 gemm | r-einsum | i-einsum -------------------------
        if (warp < BC) {
            const int b = warp;
            float acc = 0.f;
#pragma unroll 8
            for (int k = 0; k < 64; k++) acc += s_tov0[b][k] * g_sigWrT[k * 32 + lane];
            s_ov1[b][lane] = acc;
        } else if (warp >= 8 && warp < 8 + BC) {
            const int b = warp - 8;
            float crv = s_c[b][lane] / fmaxf(s_rsR[b][lane], 1e-12f);
            float m2 = 0.f;
#pragma unroll 8
            for (int o = 0; o < 32; o++)
                m2 = fmaf(s_P[b][o * 32 + lane], __shfl_sync(0xffffffffu, crv, o), m2);
            s_m2[b][lane] = m2;
        } else if (warp >= 16 && warp < 18) {
            const int wloc = warp - 16;
#pragma unroll
            for (int bb2 = 0; bb2 < 2; bb2++) {
                const int b = wloc * 2 + bb2;
                float m1 = 0.f;
#pragma unroll
                for (int ii = 0; ii < 4; ii++) {
                    float sc = sfX[ii * BC + b].x / fmaxf(s_rsI[b][ii], 1e-12f);
                    m1 = fmaf(s_I[b][ii * 32 + lane], sc, m1);
                }
                s_m1[b][lane] = m1;
            }
        }
        __syncthreads();                         // B3

        // ---- P4: combine, MR gate, LN, outputs, new carry (+c-feat) --------
        if (warp < BC) {
            const int b = warp;
            float mn = s_m1[b][lane] + s_m2[b][lane];
            float o  = s_go[b][lane];
            float f  = 1.f - o;
            float x  = s_ov1[b][lane];
            float mu = wsum32(x) * (1.f / 32.f);
            float d  = x - mu;
            float var = wsum32(d * d) * (1.f / 32.f);
            float ln  = d * rsqrtf(var + 1e-5f) * r_lng + r_lnb;
            float ov2 = ln - fmaxf(ln - f, 0.f);
            float MR  = fmaxf(ov2 + 1.f - f, 0.f) + f - 1.f;
            float op  = o + MR;
            float h   = o * mn;
            float cn  = (1.f - op) * mn;
            float mf  = MR * mn;
            size_t idx = (size_t)t * BATCH * OUTDIM + (size_t)(cta * BC + b) * OUTDIM + lane;
            out_h[idx] = h;  out_c[idx] = cn; out_o[idx] = o;  out_mr[idx] = MR;
            out_op[idx] = op; out_mf[idx] = mf; out_of[idx] = h;
            s_c[b][lane] = cn;
            s_featC[lane][b] = make_float2(cn, cn);   // c-part feat for t+1
            float as = wsum32(fabsf(cn));
            if (lane == 0) s_abs[b] = as;
        }
        __syncthreads();                         // B4
        // post this CTA's |c_new| partial for step t+1 (tag+value, one store)
        if (tid == 0) {
            float p = 0.f;
#pragma unroll
            for (int b = 0; b < BC; b++) p += s_abs[b];
            ull pk = ((ull)(unsigned)(t + 2) << 32) | (ull)__float_as_uint(p);
            post_slot(g_slot + (size_t)(t + 1) * NCTA + cta, pk);
        }
    }
}

// ---------------- launch ------------------------------------------------------
extern "C" void kernel_launch(void* const* d_in, const int* in_sizes, int n_in,
                              void* d_out, int out_size) {
    const float* xm  = (const float*)d_in[0];
    const float* xa  = (const float*)d_in[1];
    const float* Wi  = (const float*)d_in[2];
    const float* bi  = (const float*)d_in[3];
    const float* Wr  = (const float*)d_in[4];
    const float* br  = (const float*)d_in[5];
    const float* Wo  = (const float*)d_in[6];
    const float* bo  = (const float*)d_in[7];
    const float* Ws  = (const float*)d_in[8];
    const float* Wrm = (const float*)d_in[9];
    const float* b0  = (const float*)d_in[10];
    const float* lng = (const float*)d_in[11];
    const float* lnb = (const float*)d_in[12];
    (void)in_sizes; (void)n_in; (void)out_size;

    prep_kernel<<<128, 256>>>(Wi, bi, Wr, br, Wo, bo, Ws, Wrm, b0);
    lstm_kernel<<<NCTA, NTHREADS>>>(xm, xa, lng, lnb, (float*)d_out);
}